// round 11
// baseline (speedup 1.0000x reference)
#include <cuda_runtime.h>
#include <cuda_fp16.h>
#include <cstdint>

#define NROWS 32768
#define KCB   4096
#define DDIM  512

#define BM 128
#define BN 128
#define BK 64                 // halves per chunk = 128 bytes = SW128 row
#define NKCH (DDIM / BK)      // 8
#define NTHREADS 128
#define MARGIN 1e-4f
#define BSCALE 4096.0f
#define INV_BSCALE (1.0f / 4096.0f)
#define NGROUPS 64            // 64-col groups

#define A_STAGE (BM * 128)    // 16384
#define B_STAGE (BN * 128)    // 16384
#define STAGE_BYTES (A_STAGE + B_STAGE)   // 32768
#define NSTAGE 3
#define SMEM_TOTAL (NSTAGE * STAGE_BYTES) // 98304

// -------- device scratch --------
__device__ __align__(16) __half gAh[(size_t)NROWS * DDIM];
__device__ __align__(16) __half gBh[(size_t)KCB * DDIM];           // pre-scaled by 4096
__device__ unsigned long long g_groupmax[(size_t)NROWS * NGROUPS]; // 16.7 MB

// -------- helpers --------
__device__ __forceinline__ uint32_t smem_u32(const void* p) {
    uint32_t a;
    asm("{ .reg .u64 t; cvta.to.shared.u64 t, %1; cvt.u32.u64 %0, t; }" : "=r"(a) : "l"(p));
    return a;
}
__device__ __forceinline__ uint32_t sw128(uint32_t b) { return b ^ ((b >> 3) & 0x70); }
__device__ __forceinline__ unsigned int f2ord(float f) {
    unsigned int u = __float_as_uint(f);
    return (u & 0x80000000u) ? ~u : (u | 0x80000000u);
}
__device__ __forceinline__ float ord2f(unsigned int o) {
    unsigned int u = (o & 0x80000000u) ? (o & 0x7FFFFFFFu) : ~o;
    return __uint_as_float(u);
}
__device__ __forceinline__ void cp_async16(uint32_t s, const void* g) {
    asm volatile("cp.async.cg.shared.global [%0], [%1], 16;"
                 :: "r"(s), "l"(__cvta_generic_to_global(g)));
}
__device__ __forceinline__ void cp_commit() { asm volatile("cp.async.commit_group;" ::: "memory"); }
template <int N> __device__ __forceinline__ void cp_wait() {
    asm volatile("cp.async.wait_group %0;" :: "n"(N) : "memory");
}
__device__ __forceinline__ void ldm_x4(uint32_t& r0, uint32_t& r1, uint32_t& r2, uint32_t& r3,
                                       uint32_t addr) {
    asm volatile("ldmatrix.sync.aligned.m8n8.x4.shared.b16 {%0,%1,%2,%3}, [%4];"
                 : "=r"(r0), "=r"(r1), "=r"(r2), "=r"(r3) : "r"(addr));
}
__device__ __forceinline__ void mma_f16(float* c, uint32_t a0, uint32_t a1, uint32_t a2,
                                        uint32_t a3, uint32_t b0, uint32_t b1) {
    asm volatile(
        "mma.sync.aligned.m16n8k16.row.col.f32.f16.f16.f32 "
        "{%0,%1,%2,%3}, {%4,%5,%6,%7}, {%8,%9}, {%0,%1,%2,%3};"
        : "+f"(c[0]), "+f"(c[1]), "+f"(c[2]), "+f"(c[3])
        : "r"(a0), "r"(a1), "r"(a2), "r"(a3), "r"(b0), "r"(b1));
}
__device__ __forceinline__ uint32_t h2u(__half2 h) { return *reinterpret_cast<uint32_t*>(&h); }

// -------- convert (merged: B rides in the DRAM-bound A pass) --------
#define A8 ((size_t)NROWS * DDIM / 8)
#define B8 ((size_t)KCB * DDIM / 8)

__global__ __launch_bounds__(512)
void convert_kernel(const float* __restrict__ A, const float* __restrict__ B) {
    size_t id = (size_t)blockIdx.x * blockDim.x + threadIdx.x;
    if (id < A8) {
        float4 f0 = ((const float4*)A)[2 * id];
        float4 f1 = ((const float4*)A)[2 * id + 1];
        uint4 o;
        o.x = h2u(__float22half2_rn(make_float2(f0.x, f0.y)));
        o.y = h2u(__float22half2_rn(make_float2(f0.z, f0.w)));
        o.z = h2u(__float22half2_rn(make_float2(f1.x, f1.y)));
        o.w = h2u(__float22half2_rn(make_float2(f1.z, f1.w)));
        ((uint4*)gAh)[id] = o;
    } else if (id < A8 + B8) {
        size_t j = id - A8;
        float4 f0 = ((const float4*)B)[2 * j];
        float4 f1 = ((const float4*)B)[2 * j + 1];
        uint4 o;
        o.x = h2u(__float22half2_rn(make_float2(f0.x * BSCALE, f0.y * BSCALE)));
        o.y = h2u(__float22half2_rn(make_float2(f0.z * BSCALE, f0.w * BSCALE)));
        o.z = h2u(__float22half2_rn(make_float2(f1.x * BSCALE, f1.y * BSCALE)));
        o.w = h2u(__float22half2_rn(make_float2(f1.z * BSCALE, f1.w * BSCALE)));
        ((uint4*)gBh)[j] = o;
    }
}

// -------- GEMM: 128x128 tile, 4 warps of 64x64, 2 CTAs/SM, reg-double-buffered --------
__global__ __launch_bounds__(NTHREADS, 2)
void gemm_f16_kernel(float* __restrict__ C) {
    extern __shared__ char smem[];
    const uint32_t sbase = smem_u32(smem);
    const int tid = threadIdx.x;
    const int wid = tid >> 5;
    const int lane = tid & 31;
    const int warpM = wid >> 1;   // 0..1
    const int warpN = wid & 1;    // 0..1

    const int rowBase = blockIdx.y * BM;
    const int colBase = blockIdx.x * BN;

    // staging addresses: 8 A + 8 B transfers per thread
    int rIdx[8];
    uint32_t swOff[8];
    int c8[8];
#pragma unroll
    for (int i = 0; i < 8; i++) {
        int idx = tid + i * NTHREADS;           // 0..1023
        rIdx[i] = idx >> 3;
        swOff[i] = sw128((idx >> 3) * 128 + (idx & 7) * 16);
        c8[i] = idx & 7;
    }

#define STAGE(ks_, st_)                                                                   \
    do {                                                                                  \
        uint32_t base_ = sbase + (st_) * STAGE_BYTES;                                     \
        _Pragma("unroll")                                                                 \
        for (int i_ = 0; i_ < 8; i_++)                                                    \
            cp_async16(base_ + swOff[i_],                                                 \
                       gAh + (size_t)(rowBase + rIdx[i_]) * DDIM + (ks_) * BK + c8[i_] * 8); \
        _Pragma("unroll")                                                                 \
        for (int i_ = 0; i_ < 8; i_++)                                                    \
            cp_async16(base_ + A_STAGE + swOff[i_],                                       \
                       gBh + (size_t)(colBase + rIdx[i_]) * DDIM + (ks_) * BK + c8[i_] * 8); \
        cp_commit();                                                                      \
    } while (0)

    // fragment addressing (byte math within 128B SW128 rows)
    const int aRowOff = (lane & 7) | (((lane >> 3) & 1) << 3);
    const int aColSel = (lane >> 4) << 4;
    const int bRowOff = (lane & 7) | (((lane >> 4) & 1) << 3);
    const int bColSel = ((lane >> 3) & 1) << 4;

    uint32_t aBase[4], aXor[4], bBase[4], bXor[4];
#pragma unroll
    for (int mi = 0; mi < 4; mi++) {
        int r = warpM * 64 + mi * 16 + aRowOff;
        aBase[mi] = r * 128;
        aXor[mi] = (r & 7) << 4;
    }
#pragma unroll
    for (int p = 0; p < 4; p++) {
        int r = warpN * 64 + p * 16 + bRowOff;
        bBase[p] = A_STAGE + r * 128;
        bXor[p] = (r & 7) << 4;
    }

    float acc[4][8][4];
#pragma unroll
    for (int mi = 0; mi < 4; mi++)
#pragma unroll
        for (int nj = 0; nj < 8; nj++)
#pragma unroll
            for (int r = 0; r < 4; r++) acc[mi][nj][r] = 0.0f;

    STAGE(0, 0);
    STAGE(1, 1);

    uint32_t af[2][4][4], bf[2][4][4];

#define LOADFRAG(dst_, buf_, kk_)                                                          \
    do {                                                                                   \
        _Pragma("unroll")                                                                  \
        for (int mi_ = 0; mi_ < 4; mi_++)                                                  \
            ldm_x4(af[dst_][mi_][0], af[dst_][mi_][1], af[dst_][mi_][2], af[dst_][mi_][3], \
                   (buf_) + aBase[mi_] + (((uint32_t)((kk_) * 32 + aColSel)) ^ aXor[mi_]));\
        _Pragma("unroll")                                                                  \
        for (int p_ = 0; p_ < 4; p_++)                                                     \
            ldm_x4(bf[dst_][p_][0], bf[dst_][p_][1], bf[dst_][p_][2], bf[dst_][p_][3],     \
                   (buf_) + bBase[p_] + (((uint32_t)((kk_) * 32 + bColSel)) ^ bXor[p_]));  \
    } while (0)

#pragma unroll
    for (int ks = 0; ks < NKCH; ks++) {
        if (ks < NKCH - 1) cp_wait<1>(); else cp_wait<0>();
        __syncthreads();
        if (ks + 2 < NKCH) STAGE(ks + 2, (ks + 2) % NSTAGE);

        const uint32_t buf = sbase + (ks % NSTAGE) * STAGE_BYTES;

        LOADFRAG(0, buf, 0);
#pragma unroll
        for (int kk = 0; kk < 4; kk++) {
            const int cur = kk & 1;
            if (kk < 3) LOADFRAG(cur ^ 1, buf, kk + 1);
#pragma unroll
            for (int mi = 0; mi < 4; mi++)
#pragma unroll
                for (int nj = 0; nj < 8; nj++)
                    mma_f16(acc[mi][nj], af[cur][mi][0], af[cur][mi][1], af[cur][mi][2],
                            af[cur][mi][3], bf[cur][nj >> 1][2 * (nj & 1)],
                            bf[cur][nj >> 1][2 * (nj & 1) + 1]);
        }
    }
#undef STAGE
#undef LOADFRAG

    // ---- epilogue: descale, store logits, one packed max per (row, 64-col tile) ----
    const int gidx = (colBase + warpN * 64) >> 6;   // 64-col group index
#pragma unroll
    for (int mi = 0; mi < 4; mi++) {
        const int rbase = rowBase + warpM * 64 + mi * 16 + (lane >> 2);
#pragma unroll
        for (int h = 0; h < 2; h++) {
            const int row = rbase + h * 8;
            float* cr = C + (size_t)row * KCB + colBase + warpN * 64 + (lane & 3) * 2;
            unsigned long long packed = 0ull;
#pragma unroll
            for (int nj = 0; nj < 8; nj++) {
                float v0 = acc[mi][nj][h * 2] * INV_BSCALE;
                float v1 = acc[mi][nj][h * 2 + 1] * INV_BSCALE;
                *(float2*)(cr + nj * 8) = make_float2(v0, v1);
                int col0 = colBase + warpN * 64 + nj * 8 + (lane & 3) * 2;
                unsigned long long p0 =
                    ((unsigned long long)f2ord(v0) << 32) | (unsigned int)(KCB - 1 - col0);
                unsigned long long p1 =
                    ((unsigned long long)f2ord(v1) << 32) | (unsigned int)(KCB - 2 - col0);
                if (p0 > packed) packed = p0;
                if (p1 > packed) packed = p1;
            }
#pragma unroll
            for (int off = 1; off <= 2; off <<= 1) {
                unsigned long long o = __shfl_xor_sync(0xffffffffu, packed, off);
                if (o > packed) packed = o;
            }
            if ((lane & 3) == 0)
                g_groupmax[(size_t)row * NGROUPS + gidx] = packed;
        }
    }
}

// -------- refine: warp/row, 64-col groupmax prune, skip rescore if single candidate --------
__global__ __launch_bounds__(256)
void refine_kernel(const float* __restrict__ A, const float* __restrict__ B,
                   const float* __restrict__ C, float* __restrict__ idx_out) {
    const int n = (blockIdx.x * blockDim.x + threadIdx.x) >> 5;
    const int lane = threadIdx.x & 31;
    if (n >= NROWS) return;

    const unsigned long long* gm = g_groupmax + (size_t)n * NGROUPS;
    unsigned long long pm[2];
#pragma unroll
    for (int j = 0; j < 2; j++) pm[j] = gm[lane + 32 * j];

    unsigned long long mx = pm[0] > pm[1] ? pm[0] : pm[1];
#pragma unroll
    for (int o = 16; o >= 1; o >>= 1) {
        unsigned long long t = __shfl_xor_sync(0xffffffffu, mx, o);
        if (t > mx) mx = t;
    }
    const float thr = ord2f((unsigned int)(mx >> 32)) - MARGIN;
    const float2* crow2 = (const float2*)(C + (size_t)n * KCB);

    // pass 1: count candidates across candidate groups (64 cols = 32 float2/lane-warp)
    int totalc = 0;
#pragma unroll
    for (int j = 0; j < 2; j++) {
        unsigned gmask = __ballot_sync(0xffffffffu, ord2f((unsigned int)(pm[j] >> 32)) >= thr);
        while (gmask) {
            int src = __ffs(gmask) - 1;
            gmask &= gmask - 1;
            int g = 32 * j + src;
            float2 v = crow2[g * 32 + lane];
            totalc += __popc(__ballot_sync(0xffffffffu, v.x >= thr));
            totalc += __popc(__ballot_sync(0xffffffffu, v.y >= thr));
        }
    }

    int bestC;
    if (totalc <= 1) {
        bestC = KCB - 1 - (int)(unsigned int)(mx & 0xffffffffull);
    } else {
        float bestV = -3.4e38f;
        bestC = KCB;
        const float* zrow = A + (size_t)n * DDIM;
#pragma unroll
        for (int j = 0; j < 2; j++) {
            unsigned gmask = __ballot_sync(0xffffffffu, ord2f((unsigned int)(pm[j] >> 32)) >= thr);
            while (gmask) {
                int src = __ffs(gmask) - 1;
                gmask &= gmask - 1;
                int g = 32 * j + src;
                float2 v = crow2[g * 32 + lane];
                unsigned mx0 = __ballot_sync(0xffffffffu, v.x >= thr);
                unsigned mx1 = __ballot_sync(0xffffffffu, v.y >= thr);
#pragma unroll
                for (int half = 0; half < 2; half++) {
                    unsigned cmask = half ? mx1 : mx0;
                    while (cmask) {
                        int cs = __ffs(cmask) - 1;
                        cmask &= cmask - 1;
                        int cc = g * 64 + cs * 2 + half;
                        const float* brow = B + (size_t)cc * DDIM;
                        float acc = 0.0f;
#pragma unroll
                        for (int q = 0; q < 16; q++)
                            acc = fmaf(zrow[lane + 32 * q], brow[lane + 32 * q], acc);
#pragma unroll
                        for (int o = 16; o >= 1; o >>= 1)
                            acc += __shfl_xor_sync(0xffffffffu, acc, o);
                        if (acc > bestV || (acc == bestV && cc < bestC)) { bestV = acc; bestC = cc; }
                    }
                }
            }
        }
    }
    if (lane == 0) idx_out[n] = (float)bestC;
}

// -------- launch --------
extern "C" void kernel_launch(void* const* d_in, const int* in_sizes, int n_in,
                              void* d_out, int out_size) {
    const float* z  = (const float*)d_in[0];   // [32768, 512]
    const float* cb = (const float*)d_in[1];   // [4096, 512]
    float* out = (float*)d_out;
    float* logits = out;
    float* idx_out = out + ((size_t)out_size - NROWS);

    cudaFuncSetAttribute(gemm_f16_kernel, cudaFuncAttributeMaxDynamicSharedMemorySize,
                         SMEM_TOTAL);

    size_t convN = A8 + B8;
    convert_kernel<<<(unsigned)((convN + 511) / 512), 512>>>(z, cb);

    dim3 grid(KCB / BN, NROWS / BM);  // (32, 256)
    gemm_f16_kernel<<<grid, NTHREADS, SMEM_TOTAL>>>(logits);

    refine_kernel<<<NROWS / 8, 256>>>(z, cb, logits, idx_out);
}

// round 12
// speedup vs baseline: 1.4605x; 1.4605x over previous
#include <cuda_runtime.h>
#include <cuda_fp16.h>
#include <cstdint>

#define NROWS 32768
#define KCB   4096
#define DDIM  512

#define BM 128
#define BN 128
#define BK 64                 // halves per chunk = 128 bytes = SW128 row
#define NKCH (DDIM / BK)      // 8
#define NTHREADS 128
#define MARGIN 1e-4f
#define BSCALE 4096.0f
#define INV_BSCALE (1.0f / 4096.0f)
#define NGROUPS (KCB / 32)    // 128

#define A_STAGE (BM * 128)    // 16384
#define B_STAGE (BN * 128)    // 16384
#define STAGE_BYTES (A_STAGE + B_STAGE)   // 32768
#define NSTAGE 3
#define SMEM_TOTAL (NSTAGE * STAGE_BYTES) // 98304

// -------- device scratch --------
__device__ __align__(16) __half gAh[(size_t)NROWS * DDIM];
__device__ __align__(16) __half gBh[(size_t)KCB * DDIM];           // pre-scaled by 4096
__device__ unsigned long long g_groupmax[(size_t)NROWS * NGROUPS]; // 33.5 MB

// -------- helpers --------
__device__ __forceinline__ uint32_t smem_u32(const void* p) {
    uint32_t a;
    asm("{ .reg .u64 t; cvta.to.shared.u64 t, %1; cvt.u32.u64 %0, t; }" : "=r"(a) : "l"(p));
    return a;
}
__device__ __forceinline__ uint32_t sw128(uint32_t b) { return b ^ ((b >> 3) & 0x70); }
__device__ __forceinline__ unsigned int f2ord(float f) {
    unsigned int u = __float_as_uint(f);
    return (u & 0x80000000u) ? ~u : (u | 0x80000000u);
}
__device__ __forceinline__ float ord2f(unsigned int o) {
    unsigned int u = (o & 0x80000000u) ? (o & 0x7FFFFFFFu) : ~o;
    return __uint_as_float(u);
}
__device__ __forceinline__ void cp_async16(uint32_t s, const void* g) {
    asm volatile("cp.async.cg.shared.global [%0], [%1], 16;"
                 :: "r"(s), "l"(__cvta_generic_to_global(g)));
}
__device__ __forceinline__ void cp_commit() { asm volatile("cp.async.commit_group;" ::: "memory"); }
template <int N> __device__ __forceinline__ void cp_wait() {
    asm volatile("cp.async.wait_group %0;" :: "n"(N) : "memory");
}
__device__ __forceinline__ void ldm_x4(uint32_t& r0, uint32_t& r1, uint32_t& r2, uint32_t& r3,
                                       uint32_t addr) {
    asm volatile("ldmatrix.sync.aligned.m8n8.x4.shared.b16 {%0,%1,%2,%3}, [%4];"
                 : "=r"(r0), "=r"(r1), "=r"(r2), "=r"(r3) : "r"(addr));
}
__device__ __forceinline__ void mma_f16(float* c, uint32_t a0, uint32_t a1, uint32_t a2,
                                        uint32_t a3, uint32_t b0, uint32_t b1) {
    asm volatile(
        "mma.sync.aligned.m16n8k16.row.col.f32.f16.f16.f32 "
        "{%0,%1,%2,%3}, {%4,%5,%6,%7}, {%8,%9}, {%0,%1,%2,%3};"
        : "+f"(c[0]), "+f"(c[1]), "+f"(c[2]), "+f"(c[3])
        : "r"(a0), "r"(a1), "r"(a2), "r"(a3), "r"(b0), "r"(b1));
}
// streaming store: logits are written once, re-read only sparsely by refine
__device__ __forceinline__ void stg_cs_f2(float* p, float x, float y) {
    asm volatile("st.global.cs.v2.f32 [%0], {%1, %2};"
                 :: "l"(__cvta_generic_to_global(p)), "f"(x), "f"(y) : "memory");
}
__device__ __forceinline__ uint32_t h2u(__half2 h) { return *reinterpret_cast<uint32_t*>(&h); }

// -------- convert --------
#define A8 ((size_t)NROWS * DDIM / 8)
#define B8 ((size_t)KCB * DDIM / 8)

__global__ __launch_bounds__(512)
void convertA_kernel(const float* __restrict__ A) {
    size_t id = (size_t)blockIdx.x * blockDim.x + threadIdx.x;
    if (id < A8) {
        float4 f0 = ((const float4*)A)[2 * id];
        float4 f1 = ((const float4*)A)[2 * id + 1];
        uint4 o;
        o.x = h2u(__float22half2_rn(make_float2(f0.x, f0.y)));
        o.y = h2u(__float22half2_rn(make_float2(f0.z, f0.w)));
        o.z = h2u(__float22half2_rn(make_float2(f1.x, f1.y)));
        o.w = h2u(__float22half2_rn(make_float2(f1.z, f1.w)));
        ((uint4*)gAh)[id] = o;
    }
}

__global__ __launch_bounds__(512)
void convertB_kernel(const float* __restrict__ B) {
    size_t j = (size_t)blockIdx.x * blockDim.x + threadIdx.x;
    if (j < B8) {
        float4 f0 = ((const float4*)B)[2 * j];
        float4 f1 = ((const float4*)B)[2 * j + 1];
        uint4 o;
        o.x = h2u(__float22half2_rn(make_float2(f0.x * BSCALE, f0.y * BSCALE)));
        o.y = h2u(__float22half2_rn(make_float2(f0.z * BSCALE, f0.w * BSCALE)));
        o.z = h2u(__float22half2_rn(make_float2(f1.x * BSCALE, f1.y * BSCALE)));
        o.w = h2u(__float22half2_rn(make_float2(f1.z * BSCALE, f1.w * BSCALE)));
        ((uint4*)gBh)[j] = o;
    }
}

// -------- GEMM: 128x128 tile, 4 warps of 64x64, 2 CTAs/SM, reg-double-buffered --------
__global__ __launch_bounds__(NTHREADS, 2)
void gemm_f16_kernel(float* __restrict__ C) {
    extern __shared__ char smem[];
    const uint32_t sbase = smem_u32(smem);
    const int tid = threadIdx.x;
    const int wid = tid >> 5;
    const int lane = tid & 31;
    const int warpM = wid >> 1;   // 0..1
    const int warpN = wid & 1;    // 0..1

    const int rowBase = blockIdx.y * BM;
    const int colBase = blockIdx.x * BN;

    // staging addresses: 8 A + 8 B transfers per thread
    int rIdx[8];
    uint32_t swOff[8];
    int c8[8];
#pragma unroll
    for (int i = 0; i < 8; i++) {
        int idx = tid + i * NTHREADS;           // 0..1023
        rIdx[i] = idx >> 3;
        swOff[i] = sw128((idx >> 3) * 128 + (idx & 7) * 16);
        c8[i] = idx & 7;
    }

#define STAGE(ks_, st_)                                                                   \
    do {                                                                                  \
        uint32_t base_ = sbase + (st_) * STAGE_BYTES;                                     \
        _Pragma("unroll")                                                                 \
        for (int i_ = 0; i_ < 8; i_++)                                                    \
            cp_async16(base_ + swOff[i_],                                                 \
                       gAh + (size_t)(rowBase + rIdx[i_]) * DDIM + (ks_) * BK + c8[i_] * 8); \
        _Pragma("unroll")                                                                 \
        for (int i_ = 0; i_ < 8; i_++)                                                    \
            cp_async16(base_ + A_STAGE + swOff[i_],                                       \
                       gBh + (size_t)(colBase + rIdx[i_]) * DDIM + (ks_) * BK + c8[i_] * 8); \
        cp_commit();                                                                      \
    } while (0)

    // fragment addressing (byte math within 128B SW128 rows)
    const int aRowOff = (lane & 7) | (((lane >> 3) & 1) << 3);
    const int aColSel = (lane >> 4) << 4;
    const int bRowOff = (lane & 7) | (((lane >> 4) & 1) << 3);
    const int bColSel = ((lane >> 3) & 1) << 4;

    uint32_t aBase[4], aXor[4], bBase[4], bXor[4];
#pragma unroll
    for (int mi = 0; mi < 4; mi++) {
        int r = warpM * 64 + mi * 16 + aRowOff;
        aBase[mi] = r * 128;
        aXor[mi] = (r & 7) << 4;
    }
#pragma unroll
    for (int p = 0; p < 4; p++) {
        int r = warpN * 64 + p * 16 + bRowOff;
        bBase[p] = A_STAGE + r * 128;
        bXor[p] = (r & 7) << 4;
    }

    float acc[4][8][4];
#pragma unroll
    for (int mi = 0; mi < 4; mi++)
#pragma unroll
        for (int nj = 0; nj < 8; nj++)
#pragma unroll
            for (int r = 0; r < 4; r++) acc[mi][nj][r] = 0.0f;

    STAGE(0, 0);
    STAGE(1, 1);

    uint32_t af[2][4][4], bf[2][4][4];

#define LOADFRAG(dst_, buf_, kk_)                                                          \
    do {                                                                                   \
        _Pragma("unroll")                                                                  \
        for (int mi_ = 0; mi_ < 4; mi_++)                                                  \
            ldm_x4(af[dst_][mi_][0], af[dst_][mi_][1], af[dst_][mi_][2], af[dst_][mi_][3], \
                   (buf_) + aBase[mi_] + (((uint32_t)((kk_) * 32 + aColSel)) ^ aXor[mi_]));\
        _Pragma("unroll")                                                                  \
        for (int p_ = 0; p_ < 4; p_++)                                                     \
            ldm_x4(bf[dst_][p_][0], bf[dst_][p_][1], bf[dst_][p_][2], bf[dst_][p_][3],     \
                   (buf_) + bBase[p_] + (((uint32_t)((kk_) * 32 + bColSel)) ^ bXor[p_]));  \
    } while (0)

#pragma unroll
    for (int ks = 0; ks < NKCH; ks++) {
        if (ks < NKCH - 1) cp_wait<1>(); else cp_wait<0>();
        __syncthreads();
        if (ks + 2 < NKCH) STAGE(ks + 2, (ks + 2) % NSTAGE);

        const uint32_t buf = sbase + (ks % NSTAGE) * STAGE_BYTES;

        LOADFRAG(0, buf, 0);
#pragma unroll
        for (int kk = 0; kk < 4; kk++) {
            const int cur = kk & 1;
            if (kk < 3) LOADFRAG(cur ^ 1, buf, kk + 1);
#pragma unroll
            for (int mi = 0; mi < 4; mi++)
#pragma unroll
                for (int nj = 0; nj < 8; nj++)
                    mma_f16(acc[mi][nj], af[cur][mi][0], af[cur][mi][1], af[cur][mi][2],
                            af[cur][mi][3], bf[cur][nj >> 1][2 * (nj & 1)],
                            bf[cur][nj >> 1][2 * (nj & 1) + 1]);
        }
    }
#undef STAGE
#undef LOADFRAG

    // ---- epilogue: descale, store logits (.cs streaming), per-(row,32-col-group) max ----
#pragma unroll
    for (int mi = 0; mi < 4; mi++) {
        const int rbase = rowBase + warpM * 64 + mi * 16 + (lane >> 2);
#pragma unroll
        for (int h = 0; h < 2; h++) {
            const int row = rbase + h * 8;
            float* cr = C + (size_t)row * KCB + colBase + warpN * 64 + (lane & 3) * 2;
#pragma unroll
            for (int g = 0; g < 2; g++) {
                unsigned long long packed = 0ull;
#pragma unroll
                for (int q = 0; q < 4; q++) {
                    const int nj = g * 4 + q;
                    float v0 = acc[mi][nj][h * 2] * INV_BSCALE;
                    float v1 = acc[mi][nj][h * 2 + 1] * INV_BSCALE;
                    stg_cs_f2(cr + nj * 8, v0, v1);
                    int col0 = colBase + warpN * 64 + nj * 8 + (lane & 3) * 2;
                    unsigned long long p0 =
                        ((unsigned long long)f2ord(v0) << 32) | (unsigned int)(KCB - 1 - col0);
                    unsigned long long p1 =
                        ((unsigned long long)f2ord(v1) << 32) | (unsigned int)(KCB - 2 - col0);
                    if (p0 > packed) packed = p0;
                    if (p1 > packed) packed = p1;
                }
#pragma unroll
                for (int off = 1; off <= 2; off <<= 1) {
                    unsigned long long o = __shfl_xor_sync(0xffffffffu, packed, off);
                    if (o > packed) packed = o;
                }
                if ((lane & 3) == 0)
                    g_groupmax[(size_t)row * NGROUPS + ((colBase + warpN * 64) >> 5) + g] = packed;
            }
        }
    }
}

// -------- refine: warp/row, groupmax prune, skip rescore if single candidate --------
__global__ __launch_bounds__(256)
void refine_kernel(const float* __restrict__ A, const float* __restrict__ B,
                   const float* __restrict__ C, float* __restrict__ idx_out) {
    const int n = (blockIdx.x * blockDim.x + threadIdx.x) >> 5;
    const int lane = threadIdx.x & 31;
    if (n >= NROWS) return;

    const unsigned long long* gm = g_groupmax + (size_t)n * NGROUPS;
    unsigned long long pm[4];
#pragma unroll
    for (int j = 0; j < 4; j++) pm[j] = gm[lane + 32 * j];

    unsigned long long mx = pm[0];
#pragma unroll
    for (int j = 1; j < 4; j++) if (pm[j] > mx) mx = pm[j];
#pragma unroll
    for (int o = 16; o >= 1; o >>= 1) {
        unsigned long long t = __shfl_xor_sync(0xffffffffu, mx, o);
        if (t > mx) mx = t;
    }
    const float thr = ord2f((unsigned int)(mx >> 32)) - MARGIN;
    const float* crow = C + (size_t)n * KCB;

    // pass 1: count candidates
    int totalc = 0;
#pragma unroll
    for (int j = 0; j < 4; j++) {
        unsigned gmask = __ballot_sync(0xffffffffu, ord2f((unsigned int)(pm[j] >> 32)) >= thr);
        while (gmask) {
            int src = __ffs(gmask) - 1;
            gmask &= gmask - 1;
            int g = 32 * j + src;
            float v = crow[g * 32 + lane];
            totalc += __popc(__ballot_sync(0xffffffffu, v >= thr));
        }
    }

    int bestC;
    if (totalc <= 1) {
        bestC = KCB - 1 - (int)(unsigned int)(mx & 0xffffffffull);
    } else {
        float bestV = -3.4e38f;
        bestC = KCB;
        const float* zrow = A + (size_t)n * DDIM;
#pragma unroll
        for (int j = 0; j < 4; j++) {
            unsigned gmask = __ballot_sync(0xffffffffu, ord2f((unsigned int)(pm[j] >> 32)) >= thr);
            while (gmask) {
                int src = __ffs(gmask) - 1;
                gmask &= gmask - 1;
                int g = 32 * j + src;
                float v = crow[g * 32 + lane];
                unsigned cmask = __ballot_sync(0xffffffffu, v >= thr);
                while (cmask) {
                    int cs = __ffs(cmask) - 1;
                    cmask &= cmask - 1;
                    int cc = g * 32 + cs;
                    const float* brow = B + (size_t)cc * DDIM;
                    float acc = 0.0f;
#pragma unroll
                    for (int q = 0; q < 16; q++)
                        acc = fmaf(zrow[lane + 32 * q], brow[lane + 32 * q], acc);
#pragma unroll
                    for (int o = 16; o >= 1; o >>= 1)
                        acc += __shfl_xor_sync(0xffffffffu, acc, o);
                    if (acc > bestV || (acc == bestV && cc < bestC)) { bestV = acc; bestC = cc; }
                }
            }
        }
    }
    if (lane == 0) idx_out[n] = (float)bestC;
}

// -------- launch --------
extern "C" void kernel_launch(void* const* d_in, const int* in_sizes, int n_in,
                              void* d_out, int out_size) {
    const float* z  = (const float*)d_in[0];   // [32768, 512]
    const float* cb = (const float*)d_in[1];   // [4096, 512]
    float* out = (float*)d_out;
    float* logits = out;
    float* idx_out = out + ((size_t)out_size - NROWS);

    cudaFuncSetAttribute(gemm_f16_kernel, cudaFuncAttributeMaxDynamicSharedMemorySize,
                         SMEM_TOTAL);

    convertA_kernel<<<(unsigned)((A8 + 511) / 512), 512>>>(z);
    convertB_kernel<<<(unsigned)((B8 + 511) / 512), 512>>>(cb);

    dim3 grid(KCB / BN, NROWS / BM);  // (32, 256)
    gemm_f16_kernel<<<grid, NTHREADS, SMEM_TOTAL>>>(logits);

    refine_kernel<<<NROWS / 8, 256>>>(z, cb, logits, idx_out);
}

// round 13
// speedup vs baseline: 1.5605x; 1.0684x over previous
#include <cuda_runtime.h>
#include <cuda_fp16.h>
#include <cstdint>

#define NROWS 32768
#define KCB   4096
#define DDIM  512

#define BM 128
#define BN 128
#define BK 64                 // halves per chunk = 128 bytes = SW128 row
#define NKCH (DDIM / BK)      // 8
#define NTHREADS 128
#define MARGIN 1e-4f
#define BSCALE 4096.0f
#define INV_BSCALE (1.0f / 4096.0f)
#define NGROUPS (KCB / 32)    // 128

#define A_STAGE (BM * 128)    // 16384
#define B_STAGE (BN * 128)    // 16384
#define STAGE_BYTES (A_STAGE + B_STAGE)   // 32768
#define NSTAGE 3
#define SMEM_TOTAL (NSTAGE * STAGE_BYTES) // 98304

// -------- device scratch --------
__device__ __align__(16) __half gAh[(size_t)NROWS * DDIM];
__device__ __align__(16) __half gBh[(size_t)KCB * DDIM];        // pre-scaled by 4096
__device__ __align__(16) float g_groupmaxf[(size_t)NROWS * NGROUPS]; // 16.7 MB
__device__ unsigned long long g_rowmax[NROWS];                  // 256 KB (L2-resident)

// -------- helpers --------
__device__ __forceinline__ uint32_t smem_u32(const void* p) {
    uint32_t a;
    asm("{ .reg .u64 t; cvta.to.shared.u64 t, %1; cvt.u32.u64 %0, t; }" : "=r"(a) : "l"(p));
    return a;
}
__device__ __forceinline__ uint32_t sw128(uint32_t b) { return b ^ ((b >> 3) & 0x70); }
__device__ __forceinline__ unsigned int f2ord(float f) {
    unsigned int u = __float_as_uint(f);
    return (u & 0x80000000u) ? ~u : (u | 0x80000000u);
}
__device__ __forceinline__ float ord2f(unsigned int o) {
    unsigned int u = (o & 0x80000000u) ? (o & 0x7FFFFFFFu) : ~o;
    return __uint_as_float(u);
}
__device__ __forceinline__ void cp_async16(uint32_t s, const void* g) {
    asm volatile("cp.async.cg.shared.global [%0], [%1], 16;"
                 :: "r"(s), "l"(__cvta_generic_to_global(g)));
}
__device__ __forceinline__ void cp_commit() { asm volatile("cp.async.commit_group;" ::: "memory"); }
template <int N> __device__ __forceinline__ void cp_wait() {
    asm volatile("cp.async.wait_group %0;" :: "n"(N) : "memory");
}
__device__ __forceinline__ void ldm_x4(uint32_t& r0, uint32_t& r1, uint32_t& r2, uint32_t& r3,
                                       uint32_t addr) {
    asm volatile("ldmatrix.sync.aligned.m8n8.x4.shared.b16 {%0,%1,%2,%3}, [%4];"
                 : "=r"(r0), "=r"(r1), "=r"(r2), "=r"(r3) : "r"(addr));
}
__device__ __forceinline__ void mma_f16(float* c, uint32_t a0, uint32_t a1, uint32_t a2,
                                        uint32_t a3, uint32_t b0, uint32_t b1) {
    asm volatile(
        "mma.sync.aligned.m16n8k16.row.col.f32.f16.f16.f32 "
        "{%0,%1,%2,%3}, {%4,%5,%6,%7}, {%8,%9}, {%0,%1,%2,%3};"
        : "+f"(c[0]), "+f"(c[1]), "+f"(c[2]), "+f"(c[3])
        : "r"(a0), "r"(a1), "r"(a2), "r"(a3), "r"(b0), "r"(b1));
}
__device__ __forceinline__ void stg_cs_f2(float* p, float x, float y) {
    asm volatile("st.global.cs.v2.f32 [%0], {%1, %2};"
                 :: "l"(__cvta_generic_to_global(p)), "f"(x), "f"(y) : "memory");
}
__device__ __forceinline__ uint32_t h2u(__half2 h) { return *reinterpret_cast<uint32_t*>(&h); }

// -------- convert --------
#define A8 ((size_t)NROWS * DDIM / 8)
#define B8 ((size_t)KCB * DDIM / 8)

__global__ __launch_bounds__(512)
void convertA_kernel(const float* __restrict__ A) {
    size_t id = (size_t)blockIdx.x * blockDim.x + threadIdx.x;
    if (id < A8) {
        float4 f0 = ((const float4*)A)[2 * id];
        float4 f1 = ((const float4*)A)[2 * id + 1];
        uint4 o;
        o.x = h2u(__float22half2_rn(make_float2(f0.x, f0.y)));
        o.y = h2u(__float22half2_rn(make_float2(f0.z, f0.w)));
        o.z = h2u(__float22half2_rn(make_float2(f1.x, f1.y)));
        o.w = h2u(__float22half2_rn(make_float2(f1.z, f1.w)));
        ((uint4*)gAh)[id] = o;
    }
}

__global__ __launch_bounds__(512)
void convertB_kernel(const float* __restrict__ B) {
    size_t j = (size_t)blockIdx.x * blockDim.x + threadIdx.x;
    if (j < NROWS) g_rowmax[j] = 0ull;     // zero rowmax before GEMM (same stream)
    if (j < B8) {
        float4 f0 = ((const float4*)B)[2 * j];
        float4 f1 = ((const float4*)B)[2 * j + 1];
        uint4 o;
        o.x = h2u(__float22half2_rn(make_float2(f0.x * BSCALE, f0.y * BSCALE)));
        o.y = h2u(__float22half2_rn(make_float2(f0.z * BSCALE, f0.w * BSCALE)));
        o.z = h2u(__float22half2_rn(make_float2(f1.x * BSCALE, f1.y * BSCALE)));
        o.w = h2u(__float22half2_rn(make_float2(f1.z * BSCALE, f1.w * BSCALE)));
        ((uint4*)gBh)[j] = o;
    }
}

// -------- GEMM: 128x128 tile, 4 warps of 64x64, 2 CTAs/SM, reg-double-buffered --------
__global__ __launch_bounds__(NTHREADS, 2)
void gemm_f16_kernel(float* __restrict__ C) {
    extern __shared__ char smem[];
    const uint32_t sbase = smem_u32(smem);
    const int tid = threadIdx.x;
    const int wid = tid >> 5;
    const int lane = tid & 31;
    const int warpM = wid >> 1;   // 0..1
    const int warpN = wid & 1;    // 0..1

    const int rowBase = blockIdx.y * BM;
    const int colBase = blockIdx.x * BN;

    // staging addresses: 8 A + 8 B transfers per thread
    int rIdx[8];
    uint32_t swOff[8];
    int c8[8];
#pragma unroll
    for (int i = 0; i < 8; i++) {
        int idx = tid + i * NTHREADS;           // 0..1023
        rIdx[i] = idx >> 3;
        swOff[i] = sw128((idx >> 3) * 128 + (idx & 7) * 16);
        c8[i] = idx & 7;
    }

#define STAGE(ks_, st_)                                                                   \
    do {                                                                                  \
        uint32_t base_ = sbase + (st_) * STAGE_BYTES;                                     \
        _Pragma("unroll")                                                                 \
        for (int i_ = 0; i_ < 8; i_++)                                                    \
            cp_async16(base_ + swOff[i_],                                                 \
                       gAh + (size_t)(rowBase + rIdx[i_]) * DDIM + (ks_) * BK + c8[i_] * 8); \
        _Pragma("unroll")                                                                 \
        for (int i_ = 0; i_ < 8; i_++)                                                    \
            cp_async16(base_ + A_STAGE + swOff[i_],                                       \
                       gBh + (size_t)(colBase + rIdx[i_]) * DDIM + (ks_) * BK + c8[i_] * 8); \
        cp_commit();                                                                      \
    } while (0)

    // fragment addressing (byte math within 128B SW128 rows)
    const int aRowOff = (lane & 7) | (((lane >> 3) & 1) << 3);
    const int aColSel = (lane >> 4) << 4;
    const int bRowOff = (lane & 7) | (((lane >> 4) & 1) << 3);
    const int bColSel = ((lane >> 3) & 1) << 4;

    uint32_t aBase[4], aXor[4], bBase[4], bXor[4];
#pragma unroll
    for (int mi = 0; mi < 4; mi++) {
        int r = warpM * 64 + mi * 16 + aRowOff;
        aBase[mi] = r * 128;
        aXor[mi] = (r & 7) << 4;
    }
#pragma unroll
    for (int p = 0; p < 4; p++) {
        int r = warpN * 64 + p * 16 + bRowOff;
        bBase[p] = A_STAGE + r * 128;
        bXor[p] = (r & 7) << 4;
    }

    float acc[4][8][4];
#pragma unroll
    for (int mi = 0; mi < 4; mi++)
#pragma unroll
        for (int nj = 0; nj < 8; nj++)
#pragma unroll
            for (int r = 0; r < 4; r++) acc[mi][nj][r] = 0.0f;

    STAGE(0, 0);
    STAGE(1, 1);

    uint32_t af[2][4][4], bf[2][4][4];

#define LOADFRAG(dst_, buf_, kk_)                                                          \
    do {                                                                                   \
        _Pragma("unroll")                                                                  \
        for (int mi_ = 0; mi_ < 4; mi_++)                                                  \
            ldm_x4(af[dst_][mi_][0], af[dst_][mi_][1], af[dst_][mi_][2], af[dst_][mi_][3], \
                   (buf_) + aBase[mi_] + (((uint32_t)((kk_) * 32 + aColSel)) ^ aXor[mi_]));\
        _Pragma("unroll")                                                                  \
        for (int p_ = 0; p_ < 4; p_++)                                                     \
            ldm_x4(bf[dst_][p_][0], bf[dst_][p_][1], bf[dst_][p_][2], bf[dst_][p_][3],     \
                   (buf_) + bBase[p_] + (((uint32_t)((kk_) * 32 + bColSel)) ^ bXor[p_]));  \
    } while (0)

#pragma unroll
    for (int ks = 0; ks < NKCH; ks++) {
        if (ks < NKCH - 1) cp_wait<1>(); else cp_wait<0>();
        __syncthreads();
        if (ks + 2 < NKCH) STAGE(ks + 2, (ks + 2) % NSTAGE);

        const uint32_t buf = sbase + (ks % NSTAGE) * STAGE_BYTES;

        LOADFRAG(0, buf, 0);
#pragma unroll
        for (int kk = 0; kk < 4; kk++) {
            const int cur = kk & 1;
            if (kk < 3) LOADFRAG(cur ^ 1, buf, kk + 1);
#pragma unroll
            for (int mi = 0; mi < 4; mi++)
#pragma unroll
                for (int nj = 0; nj < 8; nj++)
                    mma_f16(acc[mi][nj], af[cur][mi][0], af[cur][mi][1], af[cur][mi][2],
                            af[cur][mi][3], bf[cur][nj >> 1][2 * (nj & 1)],
                            bf[cur][nj >> 1][2 * (nj & 1) + 1]);
        }
    }
#undef STAGE
#undef LOADFRAG

    // ---- epilogue: descale, store logits (.cs), float groupmax + packed rowmax atomic ----
    const int gbase = (colBase + warpN * 64) >> 5;   // first of two 32-col groups
#pragma unroll
    for (int mi = 0; mi < 4; mi++) {
        const int rbase = rowBase + warpM * 64 + mi * 16 + (lane >> 2);
#pragma unroll
        for (int h = 0; h < 2; h++) {
            const int row = rbase + h * 8;
            float* cr = C + (size_t)row * KCB + colBase + warpN * 64 + (lane & 3) * 2;
            unsigned long long packed = 0ull;
            float gmax[2];
#pragma unroll
            for (int g = 0; g < 2; g++) {
                float gm = -3.4e38f;
#pragma unroll
                for (int q = 0; q < 4; q++) {
                    const int nj = g * 4 + q;
                    float v0 = acc[mi][nj][h * 2] * INV_BSCALE;
                    float v1 = acc[mi][nj][h * 2 + 1] * INV_BSCALE;
                    stg_cs_f2(cr + nj * 8, v0, v1);
                    gm = fmaxf(gm, fmaxf(v0, v1));
                    int col0 = colBase + warpN * 64 + nj * 8 + (lane & 3) * 2;
                    unsigned long long p0 =
                        ((unsigned long long)f2ord(v0) << 32) | (unsigned int)(KCB - 1 - col0);
                    unsigned long long p1 =
                        ((unsigned long long)f2ord(v1) << 32) | (unsigned int)(KCB - 2 - col0);
                    if (p0 > packed) packed = p0;
                    if (p1 > packed) packed = p1;
                }
                gmax[g] = gm;
            }
#pragma unroll
            for (int off = 1; off <= 2; off <<= 1) {
                unsigned long long o = __shfl_xor_sync(0xffffffffu, packed, off);
                if (o > packed) packed = o;
                gmax[0] = fmaxf(gmax[0], __shfl_xor_sync(0xffffffffu, gmax[0], off));
                gmax[1] = fmaxf(gmax[1], __shfl_xor_sync(0xffffffffu, gmax[1], off));
            }
            if ((lane & 3) == 0) {
                *(float2*)(g_groupmaxf + (size_t)row * NGROUPS + gbase) =
                    make_float2(gmax[0], gmax[1]);
                atomicMax(&g_rowmax[row], packed);
            }
        }
    }
}

// -------- refine: warp/row, float-groupmax prune + rowmax shortcut --------
__global__ __launch_bounds__(256)
void refine_kernel(const float* __restrict__ A, const float* __restrict__ B,
                   const float* __restrict__ C, float* __restrict__ idx_out) {
    const int n = (blockIdx.x * blockDim.x + threadIdx.x) >> 5;
    const int lane = threadIdx.x & 31;
    if (n >= NROWS) return;

    const unsigned long long mx = g_rowmax[n];           // broadcast load
    const float thr = ord2f((unsigned int)(mx >> 32)) - MARGIN;

    // 128 group maxima: one float4 per lane, groups lane*4..lane*4+3
    const float4 gm4 = ((const float4*)(g_groupmaxf + (size_t)n * NGROUPS))[lane];
    float gmv[4] = {gm4.x, gm4.y, gm4.z, gm4.w};
    const float* crow = C + (size_t)n * KCB;

    // pass 1: count candidates in qualifying groups
    int totalc = 0;
#pragma unroll
    for (int q = 0; q < 4; q++) {
        unsigned gmask = __ballot_sync(0xffffffffu, gmv[q] >= thr);
        while (gmask) {
            int src = __ffs(gmask) - 1;
            gmask &= gmask - 1;
            int g = src * 4 + q;
            float v = crow[g * 32 + lane];
            totalc += __popc(__ballot_sync(0xffffffffu, v >= thr));
        }
    }

    int bestC;
    if (totalc <= 1) {
        bestC = KCB - 1 - (int)(unsigned int)(mx & 0xffffffffull);
    } else {
        float bestV = -3.4e38f;
        bestC = KCB;
        const float* zrow = A + (size_t)n * DDIM;
#pragma unroll
        for (int q = 0; q < 4; q++) {
            unsigned gmask = __ballot_sync(0xffffffffu, gmv[q] >= thr);
            while (gmask) {
                int src = __ffs(gmask) - 1;
                gmask &= gmask - 1;
                int g = src * 4 + q;
                float v = crow[g * 32 + lane];
                unsigned cmask = __ballot_sync(0xffffffffu, v >= thr);
                while (cmask) {
                    int cs = __ffs(cmask) - 1;
                    cmask &= cmask - 1;
                    int cc = g * 32 + cs;
                    const float* brow = B + (size_t)cc * DDIM;
                    float acc = 0.0f;
#pragma unroll
                    for (int p = 0; p < 16; p++)
                        acc = fmaf(zrow[lane + 32 * p], brow[lane + 32 * p], acc);
#pragma unroll
                    for (int o = 16; o >= 1; o >>= 1)
                        acc += __shfl_xor_sync(0xffffffffu, acc, o);
                    if (acc > bestV || (acc == bestV && cc < bestC)) { bestV = acc; bestC = cc; }
                }
            }
        }
    }
    if (lane == 0) idx_out[n] = (float)bestC;
}

// -------- launch --------
extern "C" void kernel_launch(void* const* d_in, const int* in_sizes, int n_in,
                              void* d_out, int out_size) {
    const float* z  = (const float*)d_in[0];   // [32768, 512]
    const float* cb = (const float*)d_in[1];   // [4096, 512]
    float* out = (float*)d_out;
    float* logits = out;
    float* idx_out = out + ((size_t)out_size - NROWS);

    cudaFuncSetAttribute(gemm_f16_kernel, cudaFuncAttributeMaxDynamicSharedMemorySize,
                         SMEM_TOTAL);

    convertA_kernel<<<(unsigned)((A8 + 511) / 512), 512>>>(z);
    convertB_kernel<<<(unsigned)((B8 + 511) / 512), 512>>>(cb);

    dim3 grid(KCB / BN, NROWS / BM);  // (32, 256)
    gemm_f16_kernel<<<grid, NTHREADS, SMEM_TOTAL>>>(logits);

    refine_kernel<<<NROWS / 8, 256>>>(z, cb, logits, idx_out);
}

// round 14
// speedup vs baseline: 1.5776x; 1.0110x over previous
#include <cuda_runtime.h>
#include <cuda_fp16.h>
#include <cstdint>

#define NROWS 32768
#define KCB   4096
#define DDIM  512

#define BM 128
#define BN 128
#define BK 64                 // halves per chunk = 128 bytes = SW128 row
#define NKCH (DDIM / BK)      // 8
#define NTHREADS 128
#define MARGIN 1e-4f
#define BSCALE 4096.0f
#define INV_BSCALE (1.0f / 4096.0f)
#define NGROUPS (KCB / 32)    // 128

#define A_STAGE (BM * 128)    // 16384
#define B_STAGE (BN * 128)    // 16384
#define STAGE_BYTES (A_STAGE + B_STAGE)   // 32768
#define NSTAGE 3
#define SMEM_TOTAL (NSTAGE * STAGE_BYTES) // 98304

// -------- device scratch --------
__device__ __align__(16) __half gAh[(size_t)NROWS * DDIM];
__device__ __align__(16) __half gBh[(size_t)KCB * DDIM];        // pre-scaled by 4096
__device__ __align__(16) float g_groupmaxf[(size_t)NROWS * NGROUPS]; // 16.7 MB
__device__ unsigned long long g_rowmax[NROWS];                  // 256 KB (L2-resident)

// -------- helpers --------
__device__ __forceinline__ uint32_t smem_u32(const void* p) {
    uint32_t a;
    asm("{ .reg .u64 t; cvta.to.shared.u64 t, %1; cvt.u32.u64 %0, t; }" : "=r"(a) : "l"(p));
    return a;
}
__device__ __forceinline__ uint32_t sw128(uint32_t b) { return b ^ ((b >> 3) & 0x70); }
__device__ __forceinline__ unsigned int f2ord(float f) {
    unsigned int u = __float_as_uint(f);
    return (u & 0x80000000u) ? ~u : (u | 0x80000000u);
}
__device__ __forceinline__ float ord2f(unsigned int o) {
    unsigned int u = (o & 0x80000000u) ? (o & 0x7FFFFFFFu) : ~o;
    return __uint_as_float(u);
}
__device__ __forceinline__ void cp_async16(uint32_t s, const void* g) {
    asm volatile("cp.async.cg.shared.global [%0], [%1], 16;"
                 :: "r"(s), "l"(__cvta_generic_to_global(g)));
}
__device__ __forceinline__ void cp_commit() { asm volatile("cp.async.commit_group;" ::: "memory"); }
template <int N> __device__ __forceinline__ void cp_wait() {
    asm volatile("cp.async.wait_group %0;" :: "n"(N) : "memory");
}
__device__ __forceinline__ void ldm_x4(uint32_t& r0, uint32_t& r1, uint32_t& r2, uint32_t& r3,
                                       uint32_t addr) {
    asm volatile("ldmatrix.sync.aligned.m8n8.x4.shared.b16 {%0,%1,%2,%3}, [%4];"
                 : "=r"(r0), "=r"(r1), "=r"(r2), "=r"(r3) : "r"(addr));
}
__device__ __forceinline__ void mma_f16(float* c, uint32_t a0, uint32_t a1, uint32_t a2,
                                        uint32_t a3, uint32_t b0, uint32_t b1) {
    asm volatile(
        "mma.sync.aligned.m16n8k16.row.col.f32.f16.f16.f32 "
        "{%0,%1,%2,%3}, {%4,%5,%6,%7}, {%8,%9}, {%0,%1,%2,%3};"
        : "+f"(c[0]), "+f"(c[1]), "+f"(c[2]), "+f"(c[3])
        : "r"(a0), "r"(a1), "r"(a2), "r"(a3), "r"(b0), "r"(b1));
}
__device__ __forceinline__ void stg_cs_f2(float* p, float x, float y) {
    asm volatile("st.global.cs.v2.f32 [%0], {%1, %2};"
                 :: "l"(__cvta_generic_to_global(p)), "f"(x), "f"(y) : "memory");
}
__device__ __forceinline__ uint32_t h2u(__half2 h) { return *reinterpret_cast<uint32_t*>(&h); }

// -------- convert (merged; zeroes rowmax too) --------
#define A8 ((size_t)NROWS * DDIM / 8)
#define B8 ((size_t)KCB * DDIM / 8)

__global__ __launch_bounds__(512)
void convert_kernel(const float* __restrict__ A, const float* __restrict__ B) {
    size_t id = (size_t)blockIdx.x * blockDim.x + threadIdx.x;
    if (id < NROWS) g_rowmax[id] = 0ull;
    if (id < A8) {
        float4 f0 = ((const float4*)A)[2 * id];
        float4 f1 = ((const float4*)A)[2 * id + 1];
        uint4 o;
        o.x = h2u(__float22half2_rn(make_float2(f0.x, f0.y)));
        o.y = h2u(__float22half2_rn(make_float2(f0.z, f0.w)));
        o.z = h2u(__float22half2_rn(make_float2(f1.x, f1.y)));
        o.w = h2u(__float22half2_rn(make_float2(f1.z, f1.w)));
        ((uint4*)gAh)[id] = o;
    } else if (id < A8 + B8) {
        size_t j = id - A8;
        float4 f0 = ((const float4*)B)[2 * j];
        float4 f1 = ((const float4*)B)[2 * j + 1];
        uint4 o;
        o.x = h2u(__float22half2_rn(make_float2(f0.x * BSCALE, f0.y * BSCALE)));
        o.y = h2u(__float22half2_rn(make_float2(f0.z * BSCALE, f0.w * BSCALE)));
        o.z = h2u(__float22half2_rn(make_float2(f1.x * BSCALE, f1.y * BSCALE)));
        o.w = h2u(__float22half2_rn(make_float2(f1.z * BSCALE, f1.w * BSCALE)));
        ((uint4*)gBh)[j] = o;
    }
}

// -------- GEMM: 128x128 tile, 4 warps of 64x64, 2 CTAs/SM, reg-double-buffered --------
__global__ __launch_bounds__(NTHREADS, 2)
void gemm_f16_kernel(float* __restrict__ C) {
    extern __shared__ char smem[];
    const uint32_t sbase = smem_u32(smem);
    const int tid = threadIdx.x;
    const int wid = tid >> 5;
    const int lane = tid & 31;
    const int warpM = wid >> 1;   // 0..1
    const int warpN = wid & 1;    // 0..1

    const int rowBase = blockIdx.y * BM;
    const int colBase = blockIdx.x * BN;

    // staging addresses: 8 A + 8 B transfers per thread
    int rIdx[8];
    uint32_t swOff[8];
    int c8[8];
#pragma unroll
    for (int i = 0; i < 8; i++) {
        int idx = tid + i * NTHREADS;           // 0..1023
        rIdx[i] = idx >> 3;
        swOff[i] = sw128((idx >> 3) * 128 + (idx & 7) * 16);
        c8[i] = idx & 7;
    }

#define STAGE(ks_, st_)                                                                   \
    do {                                                                                  \
        uint32_t base_ = sbase + (st_) * STAGE_BYTES;                                     \
        _Pragma("unroll")                                                                 \
        for (int i_ = 0; i_ < 8; i_++)                                                    \
            cp_async16(base_ + swOff[i_],                                                 \
                       gAh + (size_t)(rowBase + rIdx[i_]) * DDIM + (ks_) * BK + c8[i_] * 8); \
        _Pragma("unroll")                                                                 \
        for (int i_ = 0; i_ < 8; i_++)                                                    \
            cp_async16(base_ + A_STAGE + swOff[i_],                                       \
                       gBh + (size_t)(colBase + rIdx[i_]) * DDIM + (ks_) * BK + c8[i_] * 8); \
        cp_commit();                                                                      \
    } while (0)

    // fragment addressing (byte math within 128B SW128 rows)
    const int aRowOff = (lane & 7) | (((lane >> 3) & 1) << 3);
    const int aColSel = (lane >> 4) << 4;
    const int bRowOff = (lane & 7) | (((lane >> 4) & 1) << 3);
    const int bColSel = ((lane >> 3) & 1) << 4;

    uint32_t aBase[4], aXor[4], bBase[4], bXor[4];
#pragma unroll
    for (int mi = 0; mi < 4; mi++) {
        int r = warpM * 64 + mi * 16 + aRowOff;
        aBase[mi] = r * 128;
        aXor[mi] = (r & 7) << 4;
    }
#pragma unroll
    for (int p = 0; p < 4; p++) {
        int r = warpN * 64 + p * 16 + bRowOff;
        bBase[p] = A_STAGE + r * 128;
        bXor[p] = (r & 7) << 4;
    }

    float acc[4][8][4];
#pragma unroll
    for (int mi = 0; mi < 4; mi++)
#pragma unroll
        for (int nj = 0; nj < 8; nj++)
#pragma unroll
            for (int r = 0; r < 4; r++) acc[mi][nj][r] = 0.0f;

    STAGE(0, 0);
    STAGE(1, 1);

    uint32_t af[2][4][4], bf[2][4][4];

#define LOADFRAG(dst_, buf_, kk_)                                                          \
    do {                                                                                   \
        _Pragma("unroll")                                                                  \
        for (int mi_ = 0; mi_ < 4; mi_++)                                                  \
            ldm_x4(af[dst_][mi_][0], af[dst_][mi_][1], af[dst_][mi_][2], af[dst_][mi_][3], \
                   (buf_) + aBase[mi_] + (((uint32_t)((kk_) * 32 + aColSel)) ^ aXor[mi_]));\
        _Pragma("unroll")                                                                  \
        for (int p_ = 0; p_ < 4; p_++)                                                     \
            ldm_x4(bf[dst_][p_][0], bf[dst_][p_][1], bf[dst_][p_][2], bf[dst_][p_][3],     \
                   (buf_) + bBase[p_] + (((uint32_t)((kk_) * 32 + bColSel)) ^ bXor[p_]));  \
    } while (0)

#pragma unroll
    for (int ks = 0; ks < NKCH; ks++) {
        if (ks < NKCH - 1) cp_wait<1>(); else cp_wait<0>();
        __syncthreads();
        if (ks + 2 < NKCH) STAGE(ks + 2, (ks + 2) % NSTAGE);

        const uint32_t buf = sbase + (ks % NSTAGE) * STAGE_BYTES;

        LOADFRAG(0, buf, 0);
#pragma unroll
        for (int kk = 0; kk < 4; kk++) {
            const int cur = kk & 1;
            if (kk < 3) LOADFRAG(cur ^ 1, buf, kk + 1);
#pragma unroll
            for (int mi = 0; mi < 4; mi++)
#pragma unroll
                for (int nj = 0; nj < 8; nj++)
                    mma_f16(acc[mi][nj], af[cur][mi][0], af[cur][mi][1], af[cur][mi][2],
                            af[cur][mi][3], bf[cur][nj >> 1][2 * (nj & 1)],
                            bf[cur][nj >> 1][2 * (nj & 1) + 1]);
        }
    }
#undef STAGE
#undef LOADFRAG

    // ---- epilogue: descale, store logits (.cs), float groupmax + packed rowmax atomic ----
    const int gbase = (colBase + warpN * 64) >> 5;   // first of two 32-col groups
#pragma unroll
    for (int mi = 0; mi < 4; mi++) {
        const int rbase = rowBase + warpM * 64 + mi * 16 + (lane >> 2);
#pragma unroll
        for (int h = 0; h < 2; h++) {
            const int row = rbase + h * 8;
            float* cr = C + (size_t)row * KCB + colBase + warpN * 64 + (lane & 3) * 2;
            unsigned long long packed = 0ull;
            float gmax[2];
#pragma unroll
            for (int g = 0; g < 2; g++) {
                float gm = -3.4e38f;
#pragma unroll
                for (int q = 0; q < 4; q++) {
                    const int nj = g * 4 + q;
                    float v0 = acc[mi][nj][h * 2] * INV_BSCALE;
                    float v1 = acc[mi][nj][h * 2 + 1] * INV_BSCALE;
                    stg_cs_f2(cr + nj * 8, v0, v1);
                    gm = fmaxf(gm, fmaxf(v0, v1));
                    int col0 = colBase + warpN * 64 + nj * 8 + (lane & 3) * 2;
                    unsigned long long p0 =
                        ((unsigned long long)f2ord(v0) << 32) | (unsigned int)(KCB - 1 - col0);
                    unsigned long long p1 =
                        ((unsigned long long)f2ord(v1) << 32) | (unsigned int)(KCB - 2 - col0);
                    if (p0 > packed) packed = p0;
                    if (p1 > packed) packed = p1;
                }
                gmax[g] = gm;
            }
#pragma unroll
            for (int off = 1; off <= 2; off <<= 1) {
                unsigned long long o = __shfl_xor_sync(0xffffffffu, packed, off);
                if (o > packed) packed = o;
                gmax[0] = fmaxf(gmax[0], __shfl_xor_sync(0xffffffffu, gmax[0], off));
                gmax[1] = fmaxf(gmax[1], __shfl_xor_sync(0xffffffffu, gmax[1], off));
            }
            if ((lane & 3) == 0) {
                *(float2*)(g_groupmaxf + (size_t)row * NGROUPS + gbase) =
                    make_float2(gmax[0], gmax[1]);
                atomicMax(&g_rowmax[row], packed);
            }
        }
    }
}

// -------- refine: 2 rows per warp (ILP on the latency chain) --------
__global__ __launch_bounds__(256)
void refine_kernel(const float* __restrict__ A, const float* __restrict__ B,
                   const float* __restrict__ C, float* __restrict__ idx_out) {
    const int w = (blockIdx.x * blockDim.x + threadIdx.x) >> 5;
    const int lane = threadIdx.x & 31;
    const int n0 = 2 * w;
    if (n0 >= NROWS) return;

    // issue both rows' latency-critical loads up front (independent -> MLP 2x)
    const unsigned long long mxA = g_rowmax[n0];
    const unsigned long long mxB = g_rowmax[n0 + 1];
    const float4 gmA = ((const float4*)(g_groupmaxf + (size_t)n0 * NGROUPS))[lane];
    const float4 gmB = ((const float4*)(g_groupmaxf + (size_t)(n0 + 1) * NGROUPS))[lane];

#pragma unroll
    for (int r = 0; r < 2; r++) {
        const int n = n0 + r;
        const unsigned long long mx = r ? mxB : mxA;
        const float4 gm4 = r ? gmB : gmA;
        const float thr = ord2f((unsigned int)(mx >> 32)) - MARGIN;
        float gmv[4] = {gm4.x, gm4.y, gm4.z, gm4.w};
        const float* crow = C + (size_t)n * KCB;

        // pass 1: count candidates in qualifying groups
        int totalc = 0;
#pragma unroll
        for (int q = 0; q < 4; q++) {
            unsigned gmask = __ballot_sync(0xffffffffu, gmv[q] >= thr);
            while (gmask) {
                int src = __ffs(gmask) - 1;
                gmask &= gmask - 1;
                int g = src * 4 + q;
                float v = crow[g * 32 + lane];
                totalc += __popc(__ballot_sync(0xffffffffu, v >= thr));
            }
        }

        int bestC;
        if (totalc <= 1) {
            bestC = KCB - 1 - (int)(unsigned int)(mx & 0xffffffffull);
        } else {
            float bestV = -3.4e38f;
            bestC = KCB;
            const float* zrow = A + (size_t)n * DDIM;
#pragma unroll
            for (int q = 0; q < 4; q++) {
                unsigned gmask = __ballot_sync(0xffffffffu, gmv[q] >= thr);
                while (gmask) {
                    int src = __ffs(gmask) - 1;
                    gmask &= gmask - 1;
                    int g = src * 4 + q;
                    float v = crow[g * 32 + lane];
                    unsigned cmask = __ballot_sync(0xffffffffu, v >= thr);
                    while (cmask) {
                        int cs = __ffs(cmask) - 1;
                        cmask &= cmask - 1;
                        int cc = g * 32 + cs;
                        const float* brow = B + (size_t)cc * DDIM;
                        float acc = 0.0f;
#pragma unroll
                        for (int p = 0; p < 16; p++)
                            acc = fmaf(zrow[lane + 32 * p], brow[lane + 32 * p], acc);
#pragma unroll
                        for (int o = 16; o >= 1; o >>= 1)
                            acc += __shfl_xor_sync(0xffffffffu, acc, o);
                        if (acc > bestV || (acc == bestV && cc < bestC)) { bestV = acc; bestC = cc; }
                    }
                }
            }
        }
        if (lane == 0) idx_out[n] = (float)bestC;
    }
}

// -------- launch --------
extern "C" void kernel_launch(void* const* d_in, const int* in_sizes, int n_in,
                              void* d_out, int out_size) {
    const float* z  = (const float*)d_in[0];   // [32768, 512]
    const float* cb = (const float*)d_in[1];   // [4096, 512]
    float* out = (float*)d_out;
    float* logits = out;
    float* idx_out = out + ((size_t)out_size - NROWS);

    cudaFuncSetAttribute(gemm_f16_kernel, cudaFuncAttributeMaxDynamicSharedMemorySize,
                         SMEM_TOTAL);

    size_t convN = A8 + B8;
    convert_kernel<<<(unsigned)((convN + 511) / 512), 512>>>(z, cb);

    dim3 grid(KCB / BN, NROWS / BM);  // (32, 256)
    gemm_f16_kernel<<<grid, NTHREADS, SMEM_TOTAL>>>(logits);

    refine_kernel<<<NROWS / 16, 256>>>(z, cb, logits, idx_out);
}